// round 5
// baseline (speedup 1.0000x reference)
#include <cuda_runtime.h>
#include <math_constants.h>

#define NN  1024
#define VV  32000
#define BB  16
#define TT  128
#define GG  128            // CTAs in forward kernel (all co-resident)
#define RR  (NN/GG)        // 8 rows of E_T per CTA
#define TPB 256

// ---------------- device scratch (static; no runtime alloc) ----------------
__device__ unsigned short d_ETh[NN*NN];       // bf16 exp(log_T' - rowmax), 2 MB
__device__ float          d_rowmax[NN];
__device__ float          d_rowlse[NN];
__device__ float          d_collse[NN];
__device__ float          d_piadj[NN];        // log_pi - rowmax
__device__ float          d_emitg[TT*NN*BB];  // emit - rowlse + rowmax, [t][m][b]
__device__ unsigned short d_eag[2][BB*NN];    // bf16 exp(alpha - shift), ping-pong
__device__ float          d_easum[TT*BB];     // sum_n ea per (t,b)
__device__ float          d_shift[TT*BB];     // shift used per (t,b)
__device__ unsigned       d_qcnt[TT*4];       // per-step quarter counters

// ---------------- helpers ----------------
__device__ __forceinline__ unsigned long long ffma2(
    unsigned long long a, unsigned long long b, unsigned long long c) {
    unsigned long long d;
    asm("fma.rn.f32x2 %0, %1, %2, %3;" : "=l"(d) : "l"(a), "l"(b), "l"(c));
    return d;
}
// bf16 pair (packed u32, lo = element 0) -> f32x2 (64-bit reg pair)
__device__ __forceinline__ unsigned long long bf2f32x2(unsigned u) {
    unsigned lo = u << 16, hi = u & 0xffff0000u;
    unsigned long long p;
    asm("mov.b64 %0, {%1,%2};" : "=l"(p) : "r"(lo), "r"(hi));
    return p;
}
__device__ __forceinline__ void cp_async16(unsigned dst_smem, const void* src) {
    asm volatile("cp.async.cg.shared.global [%0], [%1], 16;"
                 :: "r"(dst_smem), "l"(src));
}
__device__ __forceinline__ unsigned bf16x2pack(float lo, float hi) {
    unsigned r;
    asm("cvt.rn.bf16x2.f32 %0, %1, %2;" : "=r"(r) : "f"(hi), "f"(lo));
    return r;
}
// lane0 acquire-spin until counter reaches 32, then warp-sync
__device__ __forceinline__ void spin32(const unsigned* p) {
    if ((threadIdx.x & 31) == 0) {
        unsigned v;
        do {
            asm volatile("ld.acquire.gpu.u32 %0, [%1];" : "=r"(v) : "l"(p));
        } while (v < 32u);
    }
    __syncwarp();
}

// ---------------- prep kernels ----------------
__global__ void k_rowlse(const float* __restrict__ emis) {
    int n = blockIdx.x;
    const float* row = emis + (size_t)n * VV;
    float mx = -CUDART_INF_F, s = 0.f;
    for (int i = threadIdx.x; i < VV; i += TPB) {
        float v = row[i];
        if (v > mx) { s = s * __expf(mx - v) + 1.f; mx = v; }
        else        { s += __expf(v - mx); }
    }
    __shared__ float smx[TPB], ss[TPB];
    smx[threadIdx.x] = mx; ss[threadIdx.x] = s;
    __syncthreads();
    for (int off = TPB / 2; off; off >>= 1) {
        if (threadIdx.x < off) {
            float m1 = smx[threadIdx.x], s1 = ss[threadIdx.x];
            float m2 = smx[threadIdx.x + off], s2 = ss[threadIdx.x + off];
            float m = fmaxf(m1, m2);
            ss[threadIdx.x]  = s1 * __expf(m1 - m) + s2 * __expf(m2 - m);
            smx[threadIdx.x] = m;
        }
        __syncthreads();
    }
    if (threadIdx.x == 0) d_rowlse[n] = smx[0] + __logf(ss[0]);
}

__global__ void k_collse(const float* __restrict__ trans) {
    int col = blockIdx.x * 32 + threadIdx.x;
    int ty  = threadIdx.y;
    float mx = -CUDART_INF_F, s = 0.f;
    for (int m = ty; m < NN; m += 8) {
        float v = trans[m * NN + col];
        if (v > mx) { s = s * __expf(mx - v) + 1.f; mx = v; }
        else        { s += __expf(v - mx); }
    }
    __shared__ float smx[8][32], ss[8][32];
    smx[ty][threadIdx.x] = mx; ss[ty][threadIdx.x] = s;
    __syncthreads();
    if (ty == 0) {
        float m1 = mx, s1 = s;
        for (int j = 1; j < 8; j++) {
            float m2 = smx[j][threadIdx.x], s2 = ss[j][threadIdx.x];
            float m = fmaxf(m1, m2);
            s1 = s1 * __expf(m1 - m) + s2 * __expf(m2 - m);
            m1 = m;
        }
        d_collse[col] = m1 + __logf(s1);
    }
}

__global__ void k_prepT(const float* __restrict__ trans) {
    int m = blockIdx.x;
    const float* rowp = trans + (size_t)m * NN;
    float mx = -CUDART_INF_F;
    for (int n = threadIdx.x; n < NN; n += TPB)
        mx = fmaxf(mx, rowp[n] - d_collse[n]);
    __shared__ float smx[TPB];
    smx[threadIdx.x] = mx; __syncthreads();
    for (int off = TPB / 2; off; off >>= 1) {
        if (threadIdx.x < off)
            smx[threadIdx.x] = fmaxf(smx[threadIdx.x], smx[threadIdx.x + off]);
        __syncthreads();
    }
    float rm = smx[0];
    if (threadIdx.x == 0) d_rowmax[m] = rm;
    for (int n = threadIdx.x; n < NN; n += TPB) {
        float e = __expf(rowp[n] - d_collse[n] - rm);
        unsigned r;
        asm("cvt.rn.bf16x2.f32 %0, %1, %2;" : "=r"(r) : "f"(0.f), "f"(e));
        d_ETh[m * NN + n] = (unsigned short)(r & 0xffffu);
    }
}

__global__ void k_init(const float* __restrict__ pri) {
    int base = blockIdx.x * 128;
    if (threadIdx.x < 128) d_easum[base + threadIdx.x] = 0.f;
    if (blockIdx.x < 4 && threadIdx.x < 128)
        d_qcnt[blockIdx.x * 128 + threadIdx.x] = 0u;
    if (blockIdx.x == 0) {
        float mx = -CUDART_INF_F, s = 0.f;
        for (int i = threadIdx.x; i < NN; i += TPB) {
            float v = pri[i];
            if (v > mx) { s = s * __expf(mx - v) + 1.f; mx = v; }
            else        { s += __expf(v - mx); }
        }
        __shared__ float smx[TPB], ss[TPB];
        smx[threadIdx.x] = mx; ss[threadIdx.x] = s;
        __syncthreads();
        for (int off = TPB / 2; off; off >>= 1) {
            if (threadIdx.x < off) {
                float m1 = smx[threadIdx.x], s1 = ss[threadIdx.x];
                float m2 = smx[threadIdx.x + off], s2 = ss[threadIdx.x + off];
                float m = fmaxf(m1, m2);
                ss[threadIdx.x]  = s1 * __expf(m1 - m) + s2 * __expf(m2 - m);
                smx[threadIdx.x] = m;
            }
            __syncthreads();
        }
        __shared__ float lp;
        if (threadIdx.x == 0) lp = smx[0] + __logf(ss[0]);
        __syncthreads();
        for (int m = threadIdx.x; m < NN; m += TPB)
            d_piadj[m] = pri[m] - lp - d_rowmax[m];
    }
}

__global__ void k_gather(const float* __restrict__ emis, const int* __restrict__ x) {
    int t = blockIdx.x;
    __shared__ int tok[BB];
    if (threadIdx.x < BB) tok[threadIdx.x] = x[threadIdx.x * TT + t];
    __syncthreads();
    float* dst = d_emitg + (size_t)t * NN * BB;
    for (int i = threadIdx.x; i < NN * BB; i += TPB) {
        int m = i >> 4, b = i & 15;
        dst[i] = __ldg(&emis[(size_t)m * VV + tok[b]]) - d_rowlse[m] + d_rowmax[m];
    }
}

// ---------------- persistent forward recursion ----------------
#define FWD_SMEM (RR*NN*2 + BB*NN*2 + (2*RR*BB + RR*BB)*4)

__global__ void __launch_bounds__(TPB, 1)
k_forward(const int* __restrict__ len, float* __restrict__ out) {
    extern __shared__ char sh[];
    char*  E_shb    = sh;                            // [RR][NN] bf16, 16KB
    char*  ea_sh    = sh + RR * NN * 2;              // [BB][NN] bf16, 32KB
    float* alpha_sh = (float*)(ea_sh + BB * NN * 2); // [2][RR*BB] partials
    float* eat_sh   = alpha_sh + 2 * RR * BB;        // [RR*BB]
    __shared__ float sA[BB], sB[BB];                 // shift(t-1), shift(t)

    const int g = blockIdx.x, tid = threadIdx.x;
    const int w = tid >> 5, lane = tid & 31;
    const int nh = w >> 2;                 // n-half: warps 0-3 -> 0, 4-7 -> 1
    const int mt = w & 1, bt = (w >> 1) & 1;
    const int ltid = tid & 127;
    const int myq = g >> 5;                // this CTA's quarter/chunk
    const unsigned ea_smem = (unsigned)__cvta_generic_to_shared(ea_sh);

    // stage E_T slice (bf16, 16KB) once
    {
        const uint4* src = (const uint4*)(d_ETh + (size_t)g * RR * NN);
        uint4* dst = (uint4*)E_shb;
        for (int i = tid; i < RR * NN * 2 / 16; i += TPB) dst[i] = src[i];
    }
    if (tid < BB) { sA[tid] = 0.f; sB[tid] = 0.f; }
    // shift history registers (valid in tid<16 threads)
    float sH1 = 0.f, sH2 = 0.f;            // shift(t-1), shift(t-2)
    float lseOld = 0.f;                    // lse(t-3)
    __syncthreads();

    const int ml_f = tid >> 4, b_f = tid & 15, m_f = g * RR + ml_f;

    for (int t = 0; t < TT; t++) {
        // prefetches: emit term + easum(t-2) (ordered by prior-step acquires)
        float em = 0.f, pa = 0.f, easum2 = 0.f;
        if (tid < RR * BB) {
            em = __ldcg(&d_emitg[((size_t)t * NN + m_f) * BB + b_f]);
            if (t == 0) pa = __ldcg(&d_piadj[m_f]);
        }
        if (tid < BB && t >= 2)
            easum2 = __ldcg(&d_easum[(t - 2) * BB + tid]);

        // -------- matvec: dataflow spins + cp.async + per-half pipeline ----
        if (t > 0) {
            const unsigned* cnt = &d_qcnt[(t - 1) * 4];
            const char* src = (const char*)d_eag[(t - 1) & 1];
            // chunk c = nh*2 + cc
#pragma unroll
            for (int cc = 0; cc < 2; cc++) {
                int c = nh * 2 + cc;
                spin32(&cnt[c]);
#pragma unroll
                for (int k = 0; k < 4; k++) {
                    int idx = ltid + 128 * k;        // [0,512) 16B units
                    int b = idx >> 5, o = idx & 31;
                    unsigned off =
                        (unsigned)(b * (NN * 2) + c * 512 + o * 16);
                    cp_async16(ea_smem + off, src + off);
                }
                asm volatile("cp.async.commit_group;");
            }
            // warp 0 additionally acquires quarters 2,3 (orders easum reads)
            if (w == 0 && lane == 0) {
                unsigned v;
                do { asm volatile("ld.acquire.gpu.u32 %0,[%1];":"=r"(v):"l"(&cnt[2])); } while (v < 32u);
                do { asm volatile("ld.acquire.gpu.u32 %0,[%1];":"=r"(v):"l"(&cnt[3])); } while (v < 32u);
            }

            unsigned long long acc[4][8];
#pragma unroll
            for (int j = 0; j < 4; j++)
#pragma unroll
                for (int k = 0; k < 8; k++) acc[j][k] = 0ull;
#pragma unroll
            for (int cc = 0; cc < 2; cc++) {
                if (cc == 0) asm volatile("cp.async.wait_group 1;");
                else         asm volatile("cp.async.wait_group 0;");
                asm volatile("bar.sync %0, 128;" :: "r"(2 + nh));
                int n0 = nh * 512 + cc * 256 + lane * 8;   // 8 bf16 per lane
                uint4 ev[4];
#pragma unroll
                for (int j = 0; j < 4; j++)
                    ev[j] = *(const uint4*)(E_shb + ((mt * 4 + j) * NN + n0) * 2);
                unsigned long long e[4][4];
#pragma unroll
                for (int j = 0; j < 4; j++) {
                    e[j][0] = bf2f32x2(ev[j].x); e[j][1] = bf2f32x2(ev[j].y);
                    e[j][2] = bf2f32x2(ev[j].z); e[j][3] = bf2f32x2(ev[j].w);
                }
#pragma unroll
                for (int k = 0; k < 8; k++) {
                    uint4 av = *(const uint4*)(ea_sh + ((bt * 8 + k) * NN + n0) * 2);
                    unsigned long long a0 = bf2f32x2(av.x), a1 = bf2f32x2(av.y);
                    unsigned long long a2 = bf2f32x2(av.z), a3 = bf2f32x2(av.w);
#pragma unroll
                    for (int j = 0; j < 4; j++) {
                        acc[j][k] = ffma2(e[j][0], a0, acc[j][k]);
                        acc[j][k] = ffma2(e[j][1], a1, acc[j][k]);
                        acc[j][k] = ffma2(e[j][2], a2, acc[j][k]);
                        acc[j][k] = ffma2(e[j][3], a3, acc[j][k]);
                    }
                }
            }
            float r[4][8];
#pragma unroll
            for (int j = 0; j < 4; j++)
#pragma unroll
                for (int k = 0; k < 8; k++) {
                    float2 f = *(float2*)&acc[j][k];
                    r[j][k] = f.x + f.y;
                }
#pragma unroll
            for (int off = 16; off; off >>= 1)
#pragma unroll
                for (int j = 0; j < 4; j++)
#pragma unroll
                    for (int k = 0; k < 8; k++)
                        r[j][k] += __shfl_xor_sync(0xffffffffu, r[j][k], off);
            if (lane == 0) {
#pragma unroll
                for (int j = 0; j < 4; j++)
#pragma unroll
                    for (int k = 0; k < 8; k++)
                        alpha_sh[nh * 128 + (mt * 4 + j) * BB + bt * 8 + k] = r[j][k];
            }
        }

        // -------- shift(t) from extrapolated lse(t-2) --------
        if (tid < BB) {
            float sh_t = 0.f;
            if (t >= 2) {
                float lse2 = sH2 + __logf(easum2);           // lse(t-2)
                float d = (t >= 3) ? fminf(0.f, fmaxf(-40.f, lse2 - lseOld))
                                   : 0.f;
                sh_t = lse2 + 2.f * d;
                lseOld = lse2;
            }
            sA[tid] = sH1;
            sB[tid] = sh_t;
            sH2 = sH1; sH1 = sh_t;
            if (g == 0) d_shift[t * BB + tid] = sh_t;
        }
        __syncthreads();

        // -------- finalize: alpha -> ea (shifted) --------
        if (tid < RR * BB) {
            float A = (t == 0)
                ? (em + pa)
                : (em + sA[b_f] + __logf(alpha_sh[tid] + alpha_sh[128 + tid]));
            eat_sh[tid] = __expf(A - sB[b_f]);
        }
        __syncthreads();

        // pack bf16 pairs -> d_eag[t&1]; easum partial sums
        if (tid < 64) {
            int b = tid >> 2, q = tid & 3;
            float e0 = eat_sh[(2 * q) * BB + b];
            float e1 = eat_sh[(2 * q + 1) * BB + b];
            unsigned* dst = (unsigned*)&d_eag[t & 1][b * NN + g * RR + 2 * q];
            *dst = bf16x2pack(e0, e1);
        }
        if (tid < BB) {
            float sm = eat_sh[tid];
#pragma unroll
            for (int ml = 1; ml < RR; ml++) sm += eat_sh[ml * BB + tid];
            atomicAdd(&d_easum[t * BB + tid], sm);
        }
        __syncthreads();

        // release this CTA's quarter for step t
        if (tid == 0)
            asm volatile("red.release.gpu.add.u32 [%0], 1;"
                         :: "l"(&d_qcnt[t * 4 + myq]));
    }

    // -------- final output --------
    if (g == 0) {
        if (tid == 0) {
            const unsigned* cnt = &d_qcnt[(TT - 1) * 4];
            for (int q = 0; q < 4; q++) {
                unsigned v;
                do { asm volatile("ld.acquire.gpu.u32 %0,[%1];":"=r"(v):"l"(&cnt[q])); } while (v < 32u);
            }
        }
        __syncthreads();
        if (tid < BB) {
            int tb = len[tid] - 1;
            tb = tb < 0 ? 0 : (tb > TT - 1 ? TT - 1 : tb);
            out[tid] = __ldcg(&d_shift[tb * BB + tid]) +
                       __logf(__ldcg(&d_easum[tb * BB + tid]));
        }
    }
}

// ---------------- launch ----------------
extern "C" void kernel_launch(void* const* d_in, const int* in_sizes, int n_in,
                              void* d_out, int out_size) {
    (void)in_sizes; (void)n_in; (void)out_size;
    const float* emis  = (const float*)d_in[0];  // (N, V)
    const float* trans = (const float*)d_in[1];  // (N, N)
    const float* pri   = (const float*)d_in[2];  // (N,)
    const int*   x     = (const int*)d_in[3];    // (B, T)
    const int*   len   = (const int*)d_in[4];    // (B,)
    float*       out   = (float*)d_out;          // (B, 1)

    cudaFuncSetAttribute(k_forward, cudaFuncAttributeMaxDynamicSharedMemorySize,
                         FWD_SMEM);

    k_rowlse<<<NN, TPB>>>(emis);
    k_collse<<<NN / 32, dim3(32, 8)>>>(trans);
    k_prepT<<<NN, TPB>>>(trans);
    k_init<<<16, TPB>>>(pri);
    k_gather<<<TT, TPB>>>(emis, x);
    k_forward<<<GG, TPB, FWD_SMEM>>>(len, out);
}

// round 7
// speedup vs baseline: 1.1759x; 1.1759x over previous
#include <cuda_runtime.h>
#include <math_constants.h>

#define NN  1024
#define VV  32000
#define BB  16
#define TT  128
#define GG  128            // forward CTAs: 8 groups x 16 CTAs
#define NGRP 8
#define GSZ  16            // CTAs per group
#define RR  (NN/GSZ)       // 64 rows of E_T per CTA
#define GB  2              // batches per group
#define TPB 256

// ---------------- device scratch (static; no runtime alloc) ----------------
__device__ unsigned short d_ETh[NN*NN];       // bf16 exp(log_T' - rowmax), 2 MB
__device__ float          d_rowmax[NN];
__device__ float          d_rowlse[NN];
__device__ float          d_collse[NN];
__device__ float          d_piadj[NN];        // log_pi - rowmax
__device__ float          d_emitg[TT*BB*NN];  // emit - rowlse + rowmax, [t][b][m]
__device__ unsigned short d_eag[2][BB*NN];    // bf16 exp(alpha - shift), ping-pong
__device__ float          d_easum[TT*BB];     // sum_n ea per (t,b)
__device__ float          d_shift[TT*BB];     // shift used per (t,b)
__device__ unsigned       d_gcnt[NGRP];       // per-group barrier counters

// ---------------- helpers ----------------
__device__ __forceinline__ unsigned long long ffma2(
    unsigned long long a, unsigned long long b, unsigned long long c) {
    unsigned long long d;
    asm("fma.rn.f32x2 %0, %1, %2, %3;" : "=l"(d) : "l"(a), "l"(b), "l"(c));
    return d;
}
// bf16 pair (packed u32, lo = element 0) -> f32x2 (64-bit reg pair)
__device__ __forceinline__ unsigned long long bf2f32x2(unsigned u) {
    unsigned lo = u << 16, hi = u & 0xffff0000u;
    unsigned long long p;
    asm("mov.b64 %0, {%1,%2};" : "=l"(p) : "r"(lo), "r"(hi));
    return p;
}
__device__ __forceinline__ void cp_async16(unsigned dst_smem, const void* src) {
    asm volatile("cp.async.cg.shared.global [%0], [%1], 16;"
                 :: "r"(dst_smem), "l"(src));
}
__device__ __forceinline__ unsigned bf16x2pack(float lo, float hi) {
    unsigned r;
    asm("cvt.rn.bf16x2.f32 %0, %1, %2;" : "=r"(r) : "f"(hi), "f"(lo));
    return r;
}

// group barrier: release-arrive + acquire-spin (pattern from passing R4 kernel)
__device__ __forceinline__ void gbar(unsigned* cnt, unsigned target) {
    __syncthreads();
    if (threadIdx.x == 0) {
        asm volatile("red.release.gpu.add.u32 [%0], 1;" :: "l"(cnt));
        unsigned v;
        do {
            asm volatile("ld.acquire.gpu.u32 %0, [%1];" : "=r"(v) : "l"(cnt));
        } while (v < target);
    }
    __syncthreads();
}

// ---------------- prep kernels ----------------
__global__ void k_rowlse(const float* __restrict__ emis) {
    int n = blockIdx.x;
    const float* row = emis + (size_t)n * VV;
    float mx = -CUDART_INF_F, s = 0.f;
    for (int i = threadIdx.x; i < VV; i += TPB) {
        float v = row[i];
        if (v > mx) { s = s * __expf(mx - v) + 1.f; mx = v; }
        else        { s += __expf(v - mx); }
    }
    __shared__ float smx[TPB], ss[TPB];
    smx[threadIdx.x] = mx; ss[threadIdx.x] = s;
    __syncthreads();
    for (int off = TPB / 2; off; off >>= 1) {
        if (threadIdx.x < off) {
            float m1 = smx[threadIdx.x], s1 = ss[threadIdx.x];
            float m2 = smx[threadIdx.x + off], s2 = ss[threadIdx.x + off];
            float m = fmaxf(m1, m2);
            ss[threadIdx.x]  = s1 * __expf(m1 - m) + s2 * __expf(m2 - m);
            smx[threadIdx.x] = m;
        }
        __syncthreads();
    }
    if (threadIdx.x == 0) d_rowlse[n] = smx[0] + __logf(ss[0]);
}

__global__ void k_collse(const float* __restrict__ trans) {
    int col = blockIdx.x * 32 + threadIdx.x;
    int ty  = threadIdx.y;
    float mx = -CUDART_INF_F, s = 0.f;
    for (int m = ty; m < NN; m += 8) {
        float v = trans[m * NN + col];
        if (v > mx) { s = s * __expf(mx - v) + 1.f; mx = v; }
        else        { s += __expf(v - mx); }
    }
    __shared__ float smx[8][32], ss[8][32];
    smx[ty][threadIdx.x] = mx; ss[ty][threadIdx.x] = s;
    __syncthreads();
    if (ty == 0) {
        float m1 = mx, s1 = s;
        for (int j = 1; j < 8; j++) {
            float m2 = smx[j][threadIdx.x], s2 = ss[j][threadIdx.x];
            float m = fmaxf(m1, m2);
            s1 = s1 * __expf(m1 - m) + s2 * __expf(m2 - m);
            m1 = m;
        }
        d_collse[col] = m1 + __logf(s1);
    }
}

__global__ void k_prepT(const float* __restrict__ trans) {
    int m = blockIdx.x;
    const float* rowp = trans + (size_t)m * NN;
    float mx = -CUDART_INF_F;
    for (int n = threadIdx.x; n < NN; n += TPB)
        mx = fmaxf(mx, rowp[n] - d_collse[n]);
    __shared__ float smx[TPB];
    smx[threadIdx.x] = mx; __syncthreads();
    for (int off = TPB / 2; off; off >>= 1) {
        if (threadIdx.x < off)
            smx[threadIdx.x] = fmaxf(smx[threadIdx.x], smx[threadIdx.x + off]);
        __syncthreads();
    }
    float rm = smx[0];
    if (threadIdx.x == 0) d_rowmax[m] = rm;
    for (int n = threadIdx.x; n < NN; n += TPB) {
        float e = __expf(rowp[n] - d_collse[n] - rm);
        unsigned r;
        asm("cvt.rn.bf16x2.f32 %0, %1, %2;" : "=r"(r) : "f"(0.f), "f"(e));
        d_ETh[m * NN + n] = (unsigned short)(r & 0xffffu);
    }
}

__global__ void k_init(const float* __restrict__ pri) {
    int base = blockIdx.x * 128;
    if (threadIdx.x < 128) d_easum[base + threadIdx.x] = 0.f;
    if (blockIdx.x == 0) {
        if (threadIdx.x < NGRP) d_gcnt[threadIdx.x] = 0u;
        float mx = -CUDART_INF_F, s = 0.f;
        for (int i = threadIdx.x; i < NN; i += TPB) {
            float v = pri[i];
            if (v > mx) { s = s * __expf(mx - v) + 1.f; mx = v; }
            else        { s += __expf(v - mx); }
        }
        __shared__ float smx[TPB], ss[TPB];
        smx[threadIdx.x] = mx; ss[threadIdx.x] = s;
        __syncthreads();
        for (int off = TPB / 2; off; off >>= 1) {
            if (threadIdx.x < off) {
                float m1 = smx[threadIdx.x], s1 = ss[threadIdx.x];
                float m2 = smx[threadIdx.x + off], s2 = ss[threadIdx.x + off];
                float m = fmaxf(m1, m2);
                ss[threadIdx.x]  = s1 * __expf(m1 - m) + s2 * __expf(m2 - m);
                smx[threadIdx.x] = m;
            }
            __syncthreads();
        }
        __shared__ float lp;
        if (threadIdx.x == 0) lp = smx[0] + __logf(ss[0]);
        __syncthreads();
        for (int m = threadIdx.x; m < NN; m += TPB)
            d_piadj[m] = pri[m] - lp - d_rowmax[m];
    }
}

// emitg[t][b][m] layout
__global__ void k_gather(const float* __restrict__ emis, const int* __restrict__ x) {
    int t = blockIdx.x;
    __shared__ int tok[BB];
    if (threadIdx.x < BB) tok[threadIdx.x] = x[threadIdx.x * TT + t];
    __syncthreads();
    float* dst = d_emitg + (size_t)t * BB * NN;
    for (int i = threadIdx.x; i < BB * NN; i += TPB) {
        int b = i >> 10, m = i & (NN - 1);
        dst[i] = __ldg(&emis[(size_t)m * VV + tok[b]]) - d_rowlse[m] + d_rowmax[m];
    }
}

// ---------------- persistent forward recursion (8 independent groups) -------
// smem: E bf16 128KB + ea bf16 4KB + alpha (RR*GB floats) + wsum (8 floats)
#define FWD_SMEM (RR*NN*2 + GB*NN*2 + (RR*GB + 8)*4)

__global__ void __launch_bounds__(TPB, 1)
k_forward(const int* __restrict__ len, float* __restrict__ out) {
    extern __shared__ char sh[];
    char*  E_shb    = sh;                            // [RR][NN] bf16, 128KB
    char*  ea_sh    = sh + RR * NN * 2;              // [GB][NN] bf16, 4KB
    float* alpha_sh = (float*)(ea_sh + GB * NN * 2); // [RR][GB]
    float* wsum     = alpha_sh + RR * GB;            // [8] per-warp sums
    __shared__ float sA[GB], sB[GB];                 // shift(t-1), shift(t)

    const int g = blockIdx.x, tid = threadIdx.x;
    const int w = tid >> 5, lane = tid & 31;
    const int gg = g >> 4;                 // group 0..7
    const int ci = g & 15;                 // CTA index within group
    const int b0 = gg * GB;                // group's first batch
    unsigned* cnt = &d_gcnt[gg];
    const unsigned ea_smem = (unsigned)__cvta_generic_to_shared(ea_sh);

    // stage E_T slice: rows [ci*RR, ci*RR+RR), 128KB bf16
    {
        const uint4* src = (const uint4*)(d_ETh + (size_t)ci * RR * NN);
        uint4* dst = (uint4*)E_shb;
        for (int i = tid; i < RR * NN * 2 / 16; i += TPB) dst[i] = src[i];
    }
    if (tid < GB) { sA[tid] = 0.f; sB[tid] = 0.f; }
    float sPrev = 0.f, lseP = 0.f;         // valid in tid<GB threads
    __syncthreads();

    const int b_f = tid >> 6, r_f = tid & 63;        // finalize ids (tid<128)
    const int m_f = ci * RR + r_f;

    for (int t = 0; t < TT; t++) {
        // -------- prefetches --------
        float em = 0.f, pa = 0.f, easumP = 0.f;
        if (tid < 128) {
            em = __ldcg(&d_emitg[((size_t)t * BB + (b0 + b_f)) * NN + m_f]);
            if (t == 0) pa = __ldcg(&d_piadj[m_f]);
        }
        if (tid < GB && t >= 1)
            easumP = __ldcg(&d_easum[(t - 1) * BB + b0 + tid]);

        // -------- shift(t) from lse(t-1) --------
        if (tid < GB) {
            float sh_t = 0.f;
            if (t >= 1) {
                float lse = sPrev + __logf(easumP);          // lse(t-1)
                float d = (t >= 2) ? fminf(20.f, fmaxf(-40.f, lse - lseP))
                                   : 0.f;
                sh_t = lse + d;
                lseP = lse;
            }
            sA[tid] = sPrev;
            sB[tid] = sh_t;
            sPrev = sh_t;
        }

        // -------- matvec --------
        if (t > 0) {
            // fetch group's 4KB ea slab (one 16B per thread)
            cp_async16(ea_smem + (unsigned)tid * 16,
                       (const char*)d_eag[(t - 1) & 1] + b0 * NN * 2 + tid * 16);
            asm volatile("cp.async.commit_group;");
            asm volatile("cp.async.wait_group 0;");
            __syncthreads();

            unsigned long long acc[8][GB];
#pragma unroll
            for (int j = 0; j < 8; j++)
#pragma unroll
                for (int k = 0; k < GB; k++) acc[j][k] = 0ull;

#pragma unroll
            for (int c = 0; c < 4; c++) {
                int n0 = c * 256 + lane * 8;                 // 8 bf16 per lane
                uint4 av0 = *(const uint4*)(ea_sh + n0 * 2);
                uint4 av1 = *(const uint4*)(ea_sh + (NN + n0) * 2);
                unsigned long long a0[4], a1[4];
                a0[0] = bf2f32x2(av0.x); a0[1] = bf2f32x2(av0.y);
                a0[2] = bf2f32x2(av0.z); a0[3] = bf2f32x2(av0.w);
                a1[0] = bf2f32x2(av1.x); a1[1] = bf2f32x2(av1.y);
                a1[2] = bf2f32x2(av1.z); a1[3] = bf2f32x2(av1.w);
#pragma unroll
                for (int j = 0; j < 8; j++) {
                    uint4 ev = *(const uint4*)
                        (E_shb + ((w * 8 + j) * NN + n0) * 2);
                    unsigned long long e0 = bf2f32x2(ev.x), e1 = bf2f32x2(ev.y);
                    unsigned long long e2 = bf2f32x2(ev.z), e3 = bf2f32x2(ev.w);
                    acc[j][0] = ffma2(e0, a0[0], acc[j][0]);
                    acc[j][0] = ffma2(e1, a0[1], acc[j][0]);
                    acc[j][0] = ffma2(e2, a0[2], acc[j][0]);
                    acc[j][0] = ffma2(e3, a0[3], acc[j][0]);
                    acc[j][1] = ffma2(e0, a1[0], acc[j][1]);
                    acc[j][1] = ffma2(e1, a1[1], acc[j][1]);
                    acc[j][1] = ffma2(e2, a1[2], acc[j][1]);
                    acc[j][1] = ffma2(e3, a1[3], acc[j][1]);
                }
            }
            float r[8][GB];
#pragma unroll
            for (int j = 0; j < 8; j++)
#pragma unroll
                for (int k = 0; k < GB; k++) {
                    float2 f = *(float2*)&acc[j][k];
                    r[j][k] = f.x + f.y;
                }
#pragma unroll
            for (int off = 16; off; off >>= 1)
#pragma unroll
                for (int j = 0; j < 8; j++)
#pragma unroll
                    for (int k = 0; k < GB; k++)
                        r[j][k] += __shfl_xor_sync(0xffffffffu, r[j][k], off);
            if (lane == 0) {
#pragma unroll
                for (int j = 0; j < 8; j++)
#pragma unroll
                    for (int k = 0; k < GB; k++)
                        alpha_sh[(w * 8 + j) * GB + k] = r[j][k];
            }
        }
        __syncthreads();   // alpha_sh + sA/sB visible

        // -------- finalize: alpha -> ea (shifted), pack, reduce --------
        if (tid < 128) {
            float A = (t == 0)
                ? (em + pa)
                : (em + sA[b_f] + __logf(alpha_sh[r_f * GB + b_f]));
            float e = __expf(A - sB[b_f]);

            // pack pairs via shuffle (tid, tid+1 share b, consecutive r)
            float e1 = __shfl_down_sync(0xffffffffu, e, 1);
            if (!(tid & 1)) {
                unsigned* dst = (unsigned*)
                    ((char*)d_eag[t & 1] + ((b0 + b_f) * NN + ci * RR + r_f) * 2);
                *dst = bf16x2pack(e, e1);
            }
            // per-warp sum (warps 0,1 -> batch 0; warps 2,3 -> batch 1)
            float sm = e;
#pragma unroll
            for (int off = 16; off; off >>= 1)
                sm += __shfl_xor_sync(0xffffffffu, sm, off);
            if (lane == 0) wsum[w] = sm;
        }
        __syncthreads();
        if (tid < GB) {
            atomicAdd(&d_easum[t * BB + b0 + tid],
                      wsum[2 * tid] + wsum[2 * tid + 1]);
            if (ci == 0) d_shift[t * BB + b0 + tid] = sB[tid];
        }

        gbar(cnt, (unsigned)(t + 1) * GSZ);
    }

    // -------- group-local output --------
    if (ci == 0 && tid < GB) {
        int b = b0 + tid;
        int tb = len[b] - 1;
        tb = tb < 0 ? 0 : (tb > TT - 1 ? TT - 1 : tb);
        out[b] = __ldcg(&d_shift[tb * BB + b]) +
                 __logf(__ldcg(&d_easum[tb * BB + b]));
    }
}

// ---------------- launch ----------------
extern "C" void kernel_launch(void* const* d_in, const int* in_sizes, int n_in,
                              void* d_out, int out_size) {
    (void)in_sizes; (void)n_in; (void)out_size;
    const float* emis  = (const float*)d_in[0];  // (N, V)
    const float* trans = (const float*)d_in[1];  // (N, N)
    const float* pri   = (const float*)d_in[2];  // (N,)
    const int*   x     = (const int*)d_in[3];    // (B, T)
    const int*   len   = (const int*)d_in[4];    // (B,)
    float*       out   = (float*)d_out;          // (B, 1)

    cudaFuncSetAttribute(k_forward, cudaFuncAttributeMaxDynamicSharedMemorySize,
                         FWD_SMEM);

    k_rowlse<<<NN, TPB>>>(emis);
    k_collse<<<NN / 32, dim3(32, 8)>>>(trans);
    k_prepT<<<NN, TPB>>>(trans);
    k_init<<<16, TPB>>>(pri);
    k_gather<<<TT, TPB>>>(emis, x);
    k_forward<<<GG, TPB, FWD_SMEM>>>(len, out);
}